// round 15
// baseline (speedup 1.0000x reference)
#include <cuda_runtime.h>
#include <cuda_fp16.h>
#include <math.h>

// Problem constants
#define NVOX 32768          // 32*32*32 voxels
#define NC   64             // channels
#define DP2  36             // padded dim + extra zero ring
#define GC   32             // channels per group
#define NG   2              // groups
#define NP   27             // kernel points
#define NOFF 162            // G*P*3
#define NMSK 54             // G*P
#define NJP  320            // padded j rows: 64 inp | 162 off | 54 mask | 40 zero
#define HVOL  (DP2*DP2*DP2*GC)  // halves per group = 1492992
#define HVOL4 (HVOL/8)          // float4 (8 halves) per group
#define KDW_BLOCKS 2048
#define SAPAD 72            // sA/sB row stride in halves (conflict-free fragments)
#define SCPAD 68            // sC row stride in floats

// ---- scratch (static device globals; zero-initialized at module load) ----
__device__ __align__(256) float  g_xc[NC*NVOX];     // depthwise conv out, c-major [c][v]
__device__ __align__(256) __half g_xph[NG*HVOL];    // fp16 ring-padded projected volume
__device__ __align__(256) float  g_off[NOFF*NVOX];  // offsets, transposed [j][v]
__device__ __align__(256) float  g_mask[NMSK*NVOX]; // mask logits, transposed [j][v]
__device__ __align__(256) float  g_samp[NC*NVOX];   // sampled+masked result, c-major [c][v]
__device__ float g_part[KDW_BLOCKS*2];
__device__ float g_stats[2];
__device__ __align__(256) float g_wtT[NC*NJP];      // weights [k][j], j-reordered+padded
__device__ float g_bias[NJP];

// ---------------------------------------------------------------------------
// Kernel 0: build reordered weight matrix [k][j] + bias
// ---------------------------------------------------------------------------
__global__ void k_init(const float* __restrict__ inp_w, const float* __restrict__ off_w,
                       const float* __restrict__ mask_w,
                       const float* __restrict__ inp_b, const float* __restrict__ off_b,
                       const float* __restrict__ mask_b) {
    int gid = blockIdx.x * 256 + threadIdx.x;
    if (gid < NC * NJP) {
        int k = gid / NJP, j = gid - k * NJP;
        float v = 0.f;
        if (j < 64)       v = inp_w[k * NC + j];
        else if (j < 226) v = off_w[k * NOFF + (j - 64)];
        else if (j < 280) v = mask_w[k * NMSK + (j - 226)];
        g_wtT[gid] = v;
    }
    if (gid < NJP) {
        int j = gid;
        float b = 0.f;
        if (j < 64)       b = inp_b[j];
        else if (j < 226) b = off_b[j - 64];
        else if (j < 280) b = mask_b[j - 226];
        g_bias[j] = b;
    }
}

// ---------------------------------------------------------------------------
// Kernel 1: depthwise 3x3x3 conv via smem slab (3 z-slices + halo).
// ---------------------------------------------------------------------------
__global__ void k_dw(const float* __restrict__ x, const float* __restrict__ dw_w) {
    int bz = blockIdx.x, c = blockIdx.y;
    int tid = threadIdx.x;
    __shared__ float s[3][34][34];
    __shared__ float sh[8][2];

    const float* xs = x + c * NVOX;
    for (int i = tid; i < 3 * 34 * 34; i += 256) {
        int sl = i / 1156;
        int rem = i - sl * 1156;
        int yy = rem / 34;
        int xx = rem - yy * 34;
        int z = bz + sl - 1, y = yy - 1, xg = xx - 1;
        float val = 0.f;
        if ((unsigned)z < 32u && (unsigned)y < 32u && (unsigned)xg < 32u)
            val = xs[(z << 10) + (y << 5) + xg];
        s[sl][yy][xx] = val;
    }
    float w[27];
#pragma unroll
    for (int k = 0; k < 27; k++) w[k] = __ldg(dw_w + c * 27 + k);
    __syncthreads();

    float ls = 0.f, ls2 = 0.f;
#pragma unroll
    for (int q = 0; q < 4; q++) {
        int vloc = q * 256 + tid;
        int iy = vloc >> 5, ix = vloc & 31;
        float acc = 0.f;
#pragma unroll
        for (int kz = 0; kz < 3; kz++)
#pragma unroll
            for (int ky = 0; ky < 3; ky++)
#pragma unroll
                for (int kx = 0; kx < 3; kx++)
                    acc = fmaf(w[kz*9 + ky*3 + kx], s[kz][iy + ky][ix + kx], acc);
        g_xc[c * NVOX + (bz << 10) + vloc] = acc;
        ls += acc; ls2 += acc * acc;
    }

#pragma unroll
    for (int o = 16; o > 0; o >>= 1) {
        ls  += __shfl_down_sync(0xffffffffu, ls,  o);
        ls2 += __shfl_down_sync(0xffffffffu, ls2, o);
    }
    int lane = tid & 31, warp = tid >> 5;
    if (lane == 0) { sh[warp][0] = ls; sh[warp][1] = ls2; }
    __syncthreads();
    if (tid == 0) {
        float S = 0.f, S2 = 0.f;
#pragma unroll
        for (int i = 0; i < 8; i++) { S += sh[i][0]; S2 += sh[i][1]; }
        int bid = c * 32 + bz;
        g_part[bid * 2]     = S;
        g_part[bid * 2 + 1] = S2;
    }
}

// ---------------------------------------------------------------------------
// Kernel 2: finalize mean / rstd
// ---------------------------------------------------------------------------
__global__ void k_stats() {
    int tid = threadIdx.x;
    float s = 0.f, s2 = 0.f;
    for (int i = tid; i < KDW_BLOCKS; i += 1024) {
        float2 p = reinterpret_cast<const float2*>(g_part)[i];
        s += p.x; s2 += p.y;
    }
#pragma unroll
    for (int o = 16; o > 0; o >>= 1) {
        s  += __shfl_down_sync(0xffffffffu, s,  o);
        s2 += __shfl_down_sync(0xffffffffu, s2, o);
    }
    __shared__ float sh[32][2];
    int lane = tid & 31, wid = tid >> 5;
    if (lane == 0) { sh[wid][0] = s; sh[wid][1] = s2; }
    __syncthreads();
    if (tid == 0) {
        float S = 0.f, S2 = 0.f;
#pragma unroll
        for (int i = 0; i < 32; i++) { S += sh[i][0]; S2 += sh[i][1]; }
        float n   = (float)(NVOX * NC);
        float mu  = S / n;
        float var = S2 / n - mu * mu;
        g_stats[0] = mu;
        g_stats[1] = rsqrtf(var + 1e-5f);
    }
}

// ---------------------------------------------------------------------------
// mma helper: D += A*B, m16n8k16 fp16 -> fp32
// ---------------------------------------------------------------------------
__device__ __forceinline__ void mma16816(float* c, const unsigned* a, const unsigned* b) {
    asm volatile(
        "mma.sync.aligned.m16n8k16.row.col.f32.f16.f16.f32 "
        "{%0,%1,%2,%3}, {%4,%5,%6,%7}, {%8,%9}, {%0,%1,%2,%3};"
        : "+f"(c[0]), "+f"(c[1]), "+f"(c[2]), "+f"(c[3])
        : "r"(a[0]), "r"(a[1]), "r"(a[2]), "r"(a[3]), "r"(b[0]), "r"(b[1]));
}

__device__ __forceinline__ unsigned h2u(__half2 h) {
    return *reinterpret_cast<unsigned*>(&h);
}

// ---------------------------------------------------------------------------
// Kernel 3: tensor-core GEMM, A staged ONCE, loop over 5 j-tiles in-block.
// grid 256 blocks (128-voxel tiles), 256 threads, 8 warps m32 x n32.
// sA_raw/sA_gelu fp16 [128][72] staged once; per jt: stage B fp16 [64][72]
// (overlaid with sC [128][68] float), mma, epilogue.
// ---------------------------------------------------------------------------
__global__ void __launch_bounds__(256)
k_point(const float* __restrict__ x,
        const float* __restrict__ gn_w, const float* __restrict__ gn_b) {
    int vbase = blockIdx.x * 128;
    int tid = threadIdx.x;

    __shared__ __align__(16) __half sAraw[128 * SAPAD];   // 18432 B
    __shared__ __align__(16) __half sAg[128 * SAPAD];     // 18432 B
    __shared__ __align__(16) char bufBC[128 * SCPAD * 4]; // 34816 B: sB | sC
    __half* sB = reinterpret_cast<__half*>(bufBC);        // [64][72]
    float*  sC = reinterpret_cast<float*>(bufBC);         // [128][68]

    float mu = g_stats[0], rstd = g_stats[1];

    // ---- stage A (raw + gelu) once. thread: v-quad (tid&31), k-octet (tid>>5)
    {
        int v4 = tid & 31;
        int kb = tid >> 5;
#pragma unroll
        for (int half = 0; half < 2; half++) {
            float4 rr[4], rg[4];
#pragma unroll
            for (int kk = 0; kk < 4; kk++) {
                int k = kb * 8 + half * 4 + kk;
                rr[kk] = *reinterpret_cast<const float4*>(&x[k * NVOX + vbase + v4 * 4]);
                float gw = __ldg(gn_w + k) * rstd;
                float gb = __ldg(gn_b + k) - mu * gw;
                float4 xv = *reinterpret_cast<const float4*>(&g_xc[k * NVOX + vbase + v4 * 4]);
                float q[4] = {xv.x, xv.y, xv.z, xv.w};
#pragma unroll
                for (int e = 0; e < 4; e++) {
                    float xn = q[e] * gw + gb;
                    float u = xn + 0.044715f * xn * xn * xn;
                    q[e] = xn / (1.f + __expf(-1.5957691216057308f * u));
                }
                rg[kk] = make_float4(q[0], q[1], q[2], q[3]);
            }
#pragma unroll
            for (int e = 0; e < 4; e++) {
                const float* f0 = reinterpret_cast<const float*>(&rr[0]);
                const float* f1 = reinterpret_cast<const float*>(&rr[1]);
                const float* f2 = reinterpret_cast<const float*>(&rr[2]);
                const float* f3 = reinterpret_cast<const float*>(&rr[3]);
                uint2 u;
                u.x = h2u(__floats2half2_rn(f0[e], f1[e]));
                u.y = h2u(__floats2half2_rn(f2[e], f3[e]));
                *reinterpret_cast<uint2*>(&sAraw[(v4 * 4 + e) * SAPAD + kb * 8 + half * 4]) = u;
                const float* g0 = reinterpret_cast<const float*>(&rg[0]);
                const float* g1 = reinterpret_cast<const float*>(&rg[1]);
                const float* g2 = reinterpret_cast<const float*>(&rg[2]);
                const float* g3 = reinterpret_cast<const float*>(&rg[3]);
                uint2 ug;
                ug.x = h2u(__floats2half2_rn(g0[e], g1[e]));
                ug.y = h2u(__floats2half2_rn(g2[e], g3[e]));
                *reinterpret_cast<uint2*>(&sAg[(v4 * 4 + e) * SAPAD + kb * 8 + half * 4]) = ug;
            }
        }
    }

    int w = tid >> 5, lane = tid & 31;
    int g = lane >> 2, t4 = lane & 3;
    int m0 = (w >> 1) * 32, n0 = (w & 1) * 32;
    int tx = tid & 15, ty = tid >> 4;

#pragma unroll 1
    for (int jt = 0; jt < 5; jt++) {
        __syncthreads();   // protect bufBC (prev epilogue reads done)

        // ---- stage B: [64 j][64 k] fp16 transpose of g_wtT. threads 0..127
        if (tid < 128) {
            int j4 = tid & 15;
            int kb = tid >> 4;
#pragma unroll
            for (int half = 0; half < 2; half++) {
                float4 r[4];
#pragma unroll
                for (int kk = 0; kk < 4; kk++) {
                    int k = kb * 8 + half * 4 + kk;
                    r[kk] = *reinterpret_cast<const float4*>(&g_wtT[k * NJP + jt * 64 + j4 * 4]);
                }
#pragma unroll
                for (int e = 0; e < 4; e++) {
                    const float* f0 = reinterpret_cast<const float*>(&r[0]);
                    const float* f1 = reinterpret_cast<const float*>(&r[1]);
                    const float* f2 = reinterpret_cast<const float*>(&r[2]);
                    const float* f3 = reinterpret_cast<const float*>(&r[3]);
                    uint2 u;
                    u.x = h2u(__floats2half2_rn(f0[e], f1[e]));
                    u.y = h2u(__floats2half2_rn(f2[e], f3[e]));
                    *reinterpret_cast<uint2*>(&sB[(j4 * 4 + e) * SAPAD + kb * 8 + half * 4]) = u;
                }
            }
        }
        __syncthreads();

        // ---- mma
        const __half* sA = (jt == 0) ? sAraw : sAg;
        float c[2][4][4];
#pragma unroll
        for (int mi = 0; mi < 2; mi++)
#pragma unroll
            for (int ni = 0; ni < 4; ni++)
#pragma unroll
                for (int e = 0; e < 4; e++) c[mi][ni][e] = 0.f;

#pragma unroll
        for (int kk = 0; kk < 4; kk++) {
            int k0 = kk * 16;
            unsigned a[2][4], b[4][2];
#pragma unroll
            for (int mi = 0; mi < 2; mi++) {
                int r = m0 + mi * 16;
                a[mi][0] = *reinterpret_cast<const unsigned*>(&sA[(r + g) * SAPAD + k0 + 2 * t4]);
                a[mi][1] = *reinterpret_cast<const unsigned*>(&sA[(r + 8 + g) * SAPAD + k0 + 2 * t4]);
                a[mi][2] = *reinterpret_cast<const unsigned*>(&sA[(r + g) * SAPAD + k0 + 8 + 2 * t4]);
                a[mi][3] = *reinterpret_cast<const unsigned*>(&sA[(r + 8 + g) * SAPAD + k0 + 8 + 2 * t4]);
            }
#pragma unroll
            for (int ni = 0; ni < 4; ni++) {
                int jr = n0 + ni * 8 + g;
                b[ni][0] = *reinterpret_cast<const unsigned*>(&sB[jr * SAPAD + k0 + 2 * t4]);
                b[ni][1] = *reinterpret_cast<const unsigned*>(&sB[jr * SAPAD + k0 + 8 + 2 * t4]);
            }
#pragma unroll
            for (int mi = 0; mi < 2; mi++)
#pragma unroll
                for (int ni = 0; ni < 4; ni++)
                    mma16816(c[mi][ni], a[mi], b[ni]);
        }
        __syncthreads();   // B reads done; reuse bufBC as sC

        // ---- write C fragments to sC [128][68]
#pragma unroll
        for (int mi = 0; mi < 2; mi++)
#pragma unroll
            for (int ni = 0; ni < 4; ni++) {
                int r = m0 + mi * 16 + g;
                int cc = n0 + ni * 8 + 2 * t4;
                *reinterpret_cast<float2*>(&sC[r * SCPAD + cc]) =
                    make_float2(c[mi][ni][0], c[mi][ni][1]);
                *reinterpret_cast<float2*>(&sC[(r + 8) * SCPAD + cc]) =
                    make_float2(c[mi][ni][2], c[mi][ni][3]);
            }
        __syncthreads();

        // ---- epilogue
        float acc[8][4];
#pragma unroll
        for (int vi = 0; vi < 8; vi++) {
            int vloc = ((vi & 4) << 4) + tx * 4 + (vi & 3);
            float4 q = *reinterpret_cast<float4*>(&sC[vloc * SCPAD + ty * 4]);
            acc[vi][0] = q.x; acc[vi][1] = q.y; acc[vi][2] = q.z; acc[vi][3] = q.w;
        }

        if (jt == 0) {
            int o = ty * 4;
            int gg = o >> 5, ch = o & 31;
            float4 b4 = *reinterpret_cast<const float4*>(&g_bias[o]);
#pragma unroll
            for (int vi = 0; vi < 8; vi++) {
                int v = vbase + ((vi & 4) << 4) + tx * 4 + (vi & 3);
                int iz = v >> 10, iy = (v >> 5) & 31, ix = v & 31;
                int pos = (((gg * DP2 + iz + 2) * DP2 + iy + 2) * DP2 + ix + 2);
                __half2 h01 = __floats2half2_rn(acc[vi][0] + b4.x, acc[vi][1] + b4.y);
                __half2 h23 = __floats2half2_rn(acc[vi][2] + b4.z, acc[vi][3] + b4.w);
                uint2 u;
                u.x = h2u(h01);
                u.y = h2u(h23);
                *reinterpret_cast<uint2*>(&g_xph[(pos << 5) + ch]) = u;
            }
        } else {
#pragma unroll
            for (int jj = 0; jj < 4; jj++) {
                int j = jt * 64 + ty * 4 + jj;
                float* dst;
                if (j < 226)      dst = g_off  + (j - 64)  * NVOX;
                else if (j < 280) dst = g_mask + (j - 226) * NVOX;
                else continue;
                float bj = g_bias[j];
                *reinterpret_cast<float4*>(dst + vbase + tx * 4) =
                    make_float4(acc[0][jj] + bj, acc[1][jj] + bj,
                                acc[2][jj] + bj, acc[3][jj] + bj);
                *reinterpret_cast<float4*>(dst + vbase + 64 + tx * 4) =
                    make_float4(acc[4][jj] + bj, acc[5][jj] + bj,
                                acc[6][jj] + bj, acc[7][jj] + bj);
            }
        }
    }
}

// ---------------------------------------------------------------------------
// Kernel 4: deformable sampling, SMEM window + HFMA2 inner loop. (R12 form)
// ---------------------------------------------------------------------------
__global__ void __launch_bounds__(256) k_samp() {
    int bid = blockIdx.x;            // 1024 = 512 tiles x 2 groups
    int gi = bid & 1;
    int tile = bid >> 1;
    int tbx = tile & 7, tby = (tile >> 3) & 7, tbz = tile >> 6;
    int tid = threadIdx.x;

    __shared__ __align__(16) __half s_win[8 * 8 * 8 * GC];  // 32KB
    __shared__ float s_off[64][81];
    __shared__ float s_m[64][28];

    int W0x = tbx * 4, W0y = tby * 4, W0z = tbz * 4;

    {
        const uint4* src = reinterpret_cast<const uint4*>(g_xph + (size_t)gi * HVOL);
        uint4* dst = reinterpret_cast<uint4*>(s_win);
#pragma unroll
        for (int i = 0; i < 8; i++) {
            int idx4 = i * 256 + tid;
            int pos = idx4 >> 2, q = idx4 & 3;
            int lz = pos >> 6, rem = pos & 63, ly = rem >> 3, lx = rem & 7;
            int gp = ((W0z + lz) * DP2 + W0y + ly) * DP2 + W0x + lx;
            dst[idx4] = src[gp * 4 + q];
        }
    }
    for (int idx = tid; idx < 64 * 81; idx += 256) {
        int j = idx >> 6, vl = idx & 63;
        int vx = tbx * 4 + (vl & 3), vy = tby * 4 + ((vl >> 2) & 3), vz = tbz * 4 + (vl >> 4);
        s_off[vl][j] = g_off[(gi * 81 + j) * NVOX + (vz << 10) + (vy << 5) + vx];
    }
    for (int idx = tid; idx < 64 * 27; idx += 256) {
        int j = idx >> 6, vl = idx & 63;
        int vx = tbx * 4 + (vl & 3), vy = tby * 4 + ((vl >> 2) & 3), vz = tbz * 4 + (vl >> 4);
        s_m[vl][j] = g_mask[(gi * 27 + j) * NVOX + (vz << 10) + (vy << 5) + vx];
    }
    __syncthreads();

    if (tid < 64) {
        float* m = s_m[tid];
        float mx = -1e30f;
#pragma unroll
        for (int p = 0; p < NP; p++) mx = fmaxf(mx, m[p]);
        float s = 0.f;
#pragma unroll
        for (int p = 0; p < NP; p++) { float e = __expf(m[p] - mx); m[p] = e; s += e; }
        float inv = 1.f / s;
#pragma unroll
        for (int p = 0; p < NP; p++) m[p] *= inv;
    }
    __syncthreads();

    int vv = tid >> 2;
    int c8 = tid & 3;
    int lxv = vv & 3, lyv = (vv >> 2) & 3, lzv = vv >> 4;

    const float4* win4 = reinterpret_cast<const float4*>(s_win);
    const float4* vol4 = reinterpret_cast<const float4*>(g_xph) + (size_t)gi * HVOL4 + c8;
    const float* offp = s_off[vv];
    const float* mp   = s_m[vv];

    float acc[8];
#pragma unroll
    for (int e = 0; e < 8; e++) acc[e] = 0.f;

    int kx = 0, ky = 0, kz = 0;
#pragma unroll 1
    for (int p = 0; p < NP; p++) {
        float ox = offp[p * 3 + 0];
        float oy = offp[p * 3 + 1];
        float oz = offp[p * 3 + 2];
        float sx = (float)(lxv + kx + 1) + 0.25f * ox;
        float sy = (float)(lyv + ky + 1) + 0.5f  * oy;
        float sz = (float)(lzv + kz + 1) + 0.5f  * oz;
        if (++kx == 3) { kx = 0; if (++ky == 3) { ky = 0; ++kz; } }

        float xf = floorf(sx), yf = floorf(sy), zf = floorf(sz);
        float fx = sx - xf, fy = sy - yf, fz = sz - zf;
        int x0 = (int)xf, y0 = (int)yf, z0 = (int)zf;

        float4 t000, t001, t010, t011, t100, t101, t110, t111;
        if ((unsigned)x0 < 7u && (unsigned)y0 < 7u && (unsigned)z0 < 7u) {
            int p000 = ((z0 * 8 + y0) * 8 + x0) * 4 + c8;
            t000 = win4[p000];       t001 = win4[p000 + 4];
            t010 = win4[p000 + 32];  t011 = win4[p000 + 36];
            t100 = win4[p000 + 256]; t101 = win4[p000 + 260];
            t110 = win4[p000 + 288]; t111 = win4[p000 + 292];
        } else {
            int gx0 = x0 + W0x, gy0 = y0 + W0y, gz0 = z0 + W0z;
            int x0c = min(max(gx0, 0), DP2 - 1),     y0c = min(max(gy0, 0), DP2 - 1);
            int z0c = min(max(gz0, 0), DP2 - 1);
            int x1c = min(max(gx0 + 1, 0), DP2 - 1), y1c = min(max(gy0 + 1, 0), DP2 - 1);
            int z1c = min(max(gz0 + 1, 0), DP2 - 1);
            int zy00 = (z0c * DP2 + y0c) * DP2;
            int zy01 = (z0c * DP2 + y1c) * DP2;
            int zy10 = (z1c * DP2 + y0c) * DP2;
            int zy11 = (z1c * DP2 + y1c) * DP2;
            t000 = vol4[(zy00 + x0c) << 2]; t001 = vol4[(zy00 + x1c) << 2];
            t010 = vol4[(zy01 + x0c) << 2]; t011 = vol4[(zy01 + x1c) << 2];
            t100 = vol4[(zy10 + x0c) << 2]; t101 = vol4[(zy10 + x1c) << 2];
            t110 = vol4[(zy11 + x0c) << 2]; t111 = vol4[(zy11 + x1c) << 2];
        }

        float gx1 = fx, gx0 = 1.f - fx;
        float gy1 = fy, gy0 = 1.f - fy;
        float gz1 = fz, gz0 = 1.f - fz;
        float w00 = gz0 * gy0, w01 = gz0 * gy1, w10 = gz1 * gy0, w11 = gz1 * gy1;

        __half2 h0 = __float2half2_rn(0.f), h1 = h0, h2 = h0, h3 = h0;
#define TAPH(T, W) { \
        __half2 wh = __float2half2_rn(W); \
        const __half2* hh = reinterpret_cast<const __half2*>(&T); \
        h0 = __hfma2(wh, hh[0], h0); h1 = __hfma2(wh, hh[1], h1); \
        h2 = __hfma2(wh, hh[2], h2); h3 = __hfma2(wh, hh[3], h3); }
        TAPH(t000, w00 * gx0) TAPH(t001, w00 * gx1)
        TAPH(t010, w01 * gx0) TAPH(t011, w01 * gx1)
        TAPH(t100, w10 * gx0) TAPH(t101, w10 * gx1)
        TAPH(t110, w11 * gx0) TAPH(t111, w11 * gx1)
#undef TAPH

        float m = mp[p];
        float2 f0 = __half22float2(h0);
        float2 f1 = __half22float2(h1);
        float2 f2 = __half22float2(h2);
        float2 f3 = __half22float2(h3);
        acc[0] = fmaf(m, f0.x, acc[0]); acc[1] = fmaf(m, f0.y, acc[1]);
        acc[2] = fmaf(m, f1.x, acc[2]); acc[3] = fmaf(m, f1.y, acc[3]);
        acc[4] = fmaf(m, f2.x, acc[4]); acc[5] = fmaf(m, f2.y, acc[5]);
        acc[6] = fmaf(m, f3.x, acc[6]); acc[7] = fmaf(m, f3.y, acc[7]);
    }

    int ix = tbx * 4 + lxv, iy = tby * 4 + lyv, iz = tbz * 4 + lzv;
    int v = (iz << 10) + (iy << 5) + ix;
    int cbase = gi * GC + c8 * 8;
#pragma unroll
    for (int e = 0; e < 8; e++)
        g_samp[(cbase + e) * NVOX + v] = acc[e];
}

// ---------------------------------------------------------------------------
// Kernel 5: output GEMM. out[v][oc] = g_samp[c][v]^T @ out_w[c][oc] + out_b.
// ---------------------------------------------------------------------------
__global__ void __launch_bounds__(256)
k_out(const float* __restrict__ out_w, const float* __restrict__ out_b,
      float* __restrict__ out) {
    int vbase = blockIdx.x * 128;
    int tid = threadIdx.x;
    __shared__ float sA[64 * 128];
    __shared__ float sB[64 * 64];

#pragma unroll
    for (int i = 0; i < 4; i++) {
        int lin = i * 1024 + tid * 4;
        *reinterpret_cast<float4*>(&sB[lin]) =
            *reinterpret_cast<const float4*>(&out_w[lin]);
    }
#pragma unroll
    for (int i = 0; i < 8; i++) {
        int lin = i * 1024 + tid * 4;
        int k = lin >> 7, vl = lin & 127;
        *reinterpret_cast<float4*>(&sA[lin]) =
            *reinterpret_cast<const float4*>(&g_samp[k * NVOX + vbase + vl]);
    }
    __syncthreads();

    int tx = tid & 15, ty = tid >> 4;
    float acc[8][4];
#pragma unroll
    for (int i = 0; i < 8; i++)
#pragma unroll
        for (int j = 0; j < 4; j++) acc[i][j] = 0.f;

    const float4* A4 = reinterpret_cast<const float4*>(sA);
    const float4* B4 = reinterpret_cast<const float4*>(sB);
#pragma unroll 8
    for (int k = 0; k < 64; k++) {
        float4 a0 = A4[k * 32 + tx];
        float4 a1 = A4[k * 32 + 16 + tx];
        float4 b  = B4[k * 16 + ty];
        float av[8] = {a0.x, a0.y, a0.z, a0.w, a1.x, a1.y, a1.z, a1.w};
        float bv[4] = {b.x, b.y, b.z, b.w};
#pragma unroll
        for (int i = 0; i < 8; i++)
#pragma unroll
            for (int j = 0; j < 4; j++)
                acc[i][j] = fmaf(av[i], bv[j], acc[i][j]);
    }

    float4 b4 = *reinterpret_cast<const float4*>(&out_b[ty * 4]);
#pragma unroll
    for (int vi = 0; vi < 8; vi++) {
        int v = vbase + ((vi & 4) << 4) + tx * 4 + (vi & 3);
        *reinterpret_cast<float4*>(&out[v * NC + ty * 4]) =
            make_float4(acc[vi][0] + b4.x, acc[vi][1] + b4.y,
                        acc[vi][2] + b4.z, acc[vi][3] + b4.w);
    }
}

// ---------------------------------------------------------------------------
extern "C" void kernel_launch(void* const* d_in, const int* in_sizes, int n_in,
                              void* d_out, int out_size) {
    const float* x      = (const float*)d_in[0];
    const float* dw_w   = (const float*)d_in[1];
    const float* gn_w   = (const float*)d_in[2];
    const float* gn_b   = (const float*)d_in[3];
    const float* inp_w  = (const float*)d_in[4];
    const float* inp_b  = (const float*)d_in[5];
    const float* off_w  = (const float*)d_in[6];
    const float* off_b  = (const float*)d_in[7];
    const float* mask_w = (const float*)d_in[8];
    const float* mask_b = (const float*)d_in[9];
    const float* out_w  = (const float*)d_in[10];
    const float* out_b  = (const float*)d_in[11];
    float* out = (float*)d_out;

    k_init<<<(NC * NJP + 255) / 256, 256>>>(inp_w, off_w, mask_w, inp_b, off_b, mask_b);
    k_dw<<<dim3(32, 64), 256>>>(x, dw_w);
    k_stats<<<1, 1024>>>();
    k_point<<<NVOX / 128, 256>>>(x, gn_w, gn_b);
    k_samp<<<1024, 256>>>();
    k_out<<<NVOX / 128, 256>>>(out_w, out_b, out);
}

// round 16
// speedup vs baseline: 1.4410x; 1.4410x over previous
#include <cuda_runtime.h>
#include <cuda_fp16.h>
#include <math.h>

// Problem constants
#define NVOX 32768          // 32*32*32 voxels
#define NC   64             // channels
#define DP2  36             // padded dim + extra zero ring
#define GC   32             // channels per group
#define NG   2              // groups
#define NP   27             // kernel points
#define NOFF 162            // G*P*3
#define NMSK 54             // G*P
#define NJP  320            // padded j rows: 64 inp | 162 off | 54 mask | 40 zero
#define HVOL  (DP2*DP2*DP2*GC)  // halves per group = 1492992
#define HVOL4 (HVOL/8)          // float4 (8 halves) per group
#define KDW_BLOCKS 2048
#define SAPAD 72            // sA/sB row stride in halves (conflict-free fragments)
#define SCPAD 68            // sC row stride in floats

// ---- scratch (static device globals; zero-initialized at module load) ----
__device__ __align__(256) float  g_xc[NC*NVOX];     // depthwise conv out, c-major [c][v]
__device__ __align__(256) __half g_xph[NG*HVOL];    // fp16 ring-padded projected volume
__device__ __align__(256) float  g_off[NOFF*NVOX];  // offsets [j][v_perm] (tile-permuted)
__device__ __align__(256) float  g_mask[NMSK*NVOX]; // mask logits [j][v_perm]
__device__ __align__(256) float  g_samp[NC*NVOX];   // sampled result [c][v_perm]
__device__ float g_part[KDW_BLOCKS*2];
__device__ float g_stats[2];
__device__ __align__(256) float g_wtT[NC*NJP];      // weights [k][j], j-reordered+padded
__device__ float g_bias[NJP];

// tile permutation: v (z,y,x) -> tile-major index (4x4x4 tiles contiguous)
__device__ __forceinline__ int permv(int v) {
    int iz = v >> 10, iy = (v >> 5) & 31, ix = v & 31;
    int t = ((iz >> 2) << 6) + ((iy >> 2) << 3) + (ix >> 2);
    int l = ((iz & 3) << 4) + ((iy & 3) << 2) + (ix & 3);
    return (t << 6) + l;
}

// ---------------------------------------------------------------------------
// Kernel 0: build reordered weight matrix [k][j] + bias
// ---------------------------------------------------------------------------
__global__ void k_init(const float* __restrict__ inp_w, const float* __restrict__ off_w,
                       const float* __restrict__ mask_w,
                       const float* __restrict__ inp_b, const float* __restrict__ off_b,
                       const float* __restrict__ mask_b) {
    int gid = blockIdx.x * 256 + threadIdx.x;
    if (gid < NC * NJP) {
        int k = gid / NJP, j = gid - k * NJP;
        float v = 0.f;
        if (j < 64)       v = inp_w[k * NC + j];
        else if (j < 226) v = off_w[k * NOFF + (j - 64)];
        else if (j < 280) v = mask_w[k * NMSK + (j - 226)];
        g_wtT[gid] = v;
    }
    if (gid < NJP) {
        int j = gid;
        float b = 0.f;
        if (j < 64)       b = inp_b[j];
        else if (j < 226) b = off_b[j - 64];
        else if (j < 280) b = mask_b[j - 226];
        g_bias[j] = b;
    }
}

// ---------------------------------------------------------------------------
// Kernel 1: depthwise 3x3x3 conv via smem slab (3 z-slices + halo).
// ---------------------------------------------------------------------------
__global__ void k_dw(const float* __restrict__ x, const float* __restrict__ dw_w) {
    int bz = blockIdx.x, c = blockIdx.y;
    int tid = threadIdx.x;
    __shared__ float s[3][34][34];
    __shared__ float sh[8][2];

    const float* xs = x + c * NVOX;
    for (int i = tid; i < 3 * 34 * 34; i += 256) {
        int sl = i / 1156;
        int rem = i - sl * 1156;
        int yy = rem / 34;
        int xx = rem - yy * 34;
        int z = bz + sl - 1, y = yy - 1, xg = xx - 1;
        float val = 0.f;
        if ((unsigned)z < 32u && (unsigned)y < 32u && (unsigned)xg < 32u)
            val = xs[(z << 10) + (y << 5) + xg];
        s[sl][yy][xx] = val;
    }
    float w[27];
#pragma unroll
    for (int k = 0; k < 27; k++) w[k] = __ldg(dw_w + c * 27 + k);
    __syncthreads();

    float ls = 0.f, ls2 = 0.f;
#pragma unroll
    for (int q = 0; q < 4; q++) {
        int vloc = q * 256 + tid;
        int iy = vloc >> 5, ix = vloc & 31;
        float acc = 0.f;
#pragma unroll
        for (int kz = 0; kz < 3; kz++)
#pragma unroll
            for (int ky = 0; ky < 3; ky++)
#pragma unroll
                for (int kx = 0; kx < 3; kx++)
                    acc = fmaf(w[kz*9 + ky*3 + kx], s[kz][iy + ky][ix + kx], acc);
        g_xc[c * NVOX + (bz << 10) + vloc] = acc;
        ls += acc; ls2 += acc * acc;
    }

#pragma unroll
    for (int o = 16; o > 0; o >>= 1) {
        ls  += __shfl_down_sync(0xffffffffu, ls,  o);
        ls2 += __shfl_down_sync(0xffffffffu, ls2, o);
    }
    int lane = tid & 31, warp = tid >> 5;
    if (lane == 0) { sh[warp][0] = ls; sh[warp][1] = ls2; }
    __syncthreads();
    if (tid == 0) {
        float S = 0.f, S2 = 0.f;
#pragma unroll
        for (int i = 0; i < 8; i++) { S += sh[i][0]; S2 += sh[i][1]; }
        int bid = c * 32 + bz;
        g_part[bid * 2]     = S;
        g_part[bid * 2 + 1] = S2;
    }
}

// ---------------------------------------------------------------------------
// Kernel 2: finalize mean / rstd
// ---------------------------------------------------------------------------
__global__ void k_stats() {
    int tid = threadIdx.x;
    float s = 0.f, s2 = 0.f;
    for (int i = tid; i < KDW_BLOCKS; i += 1024) {
        float2 p = reinterpret_cast<const float2*>(g_part)[i];
        s += p.x; s2 += p.y;
    }
#pragma unroll
    for (int o = 16; o > 0; o >>= 1) {
        s  += __shfl_down_sync(0xffffffffu, s,  o);
        s2 += __shfl_down_sync(0xffffffffu, s2, o);
    }
    __shared__ float sh[32][2];
    int lane = tid & 31, wid = tid >> 5;
    if (lane == 0) { sh[wid][0] = s; sh[wid][1] = s2; }
    __syncthreads();
    if (tid == 0) {
        float S = 0.f, S2 = 0.f;
#pragma unroll
        for (int i = 0; i < 32; i++) { S += sh[i][0]; S2 += sh[i][1]; }
        float n   = (float)(NVOX * NC);
        float mu  = S / n;
        float var = S2 / n - mu * mu;
        g_stats[0] = mu;
        g_stats[1] = rsqrtf(var + 1e-5f);
    }
}

// ---------------------------------------------------------------------------
// mma helper: D += A*B, m16n8k16 fp16 -> fp32
// ---------------------------------------------------------------------------
__device__ __forceinline__ void mma16816(float* c, const unsigned* a, const unsigned* b) {
    asm volatile(
        "mma.sync.aligned.m16n8k16.row.col.f32.f16.f16.f32 "
        "{%0,%1,%2,%3}, {%4,%5,%6,%7}, {%8,%9}, {%0,%1,%2,%3};"
        : "+f"(c[0]), "+f"(c[1]), "+f"(c[2]), "+f"(c[3])
        : "r"(a[0]), "r"(a[1]), "r"(a[2]), "r"(a[3]), "r"(b[0]), "r"(b[1]));
}

__device__ __forceinline__ unsigned h2u(__half2 h) {
    return *reinterpret_cast<unsigned*>(&h);
}

// ---------------------------------------------------------------------------
// Kernel 3: tensor-core GEMM (R14-proven form). grid (256, 5), 256 threads.
// jt>=1 stores go through the tile permutation (float4 quads stay contiguous).
// ---------------------------------------------------------------------------
__global__ void __launch_bounds__(256)
k_point(const float* __restrict__ x,
        const float* __restrict__ gn_w, const float* __restrict__ gn_b) {
    int jt = blockIdx.y;
    int vbase = blockIdx.x * 128;
    int tid = threadIdx.x;

    __shared__ __align__(16) char buf[128 * SCPAD * 4];   // 34816 B
    __half* sA = reinterpret_cast<__half*>(buf);                    // [128][72]
    __half* sB = reinterpret_cast<__half*>(buf + 128 * SAPAD * 2);  // [64][72]
    float*  sC = reinterpret_cast<float*>(buf);                     // [128][68]

    float mu = g_stats[0], rstd = g_stats[1];

    // ---- stage A: [128 v][64 k] fp16. thread: v-quad (tid&31), k-octet (tid>>5)
    {
        int v4 = tid & 31;
        int kb = tid >> 5;
#pragma unroll
        for (int half = 0; half < 2; half++) {
            float4 r[4];
#pragma unroll
            for (int kk = 0; kk < 4; kk++) {
                int k = kb * 8 + half * 4 + kk;
                if (jt == 0) {
                    r[kk] = *reinterpret_cast<const float4*>(&x[k * NVOX + vbase + v4 * 4]);
                } else {
                    float gw = __ldg(gn_w + k) * rstd;
                    float gb = __ldg(gn_b + k) - mu * gw;
                    float4 xv = *reinterpret_cast<const float4*>(&g_xc[k * NVOX + vbase + v4 * 4]);
                    float q[4] = {xv.x, xv.y, xv.z, xv.w};
#pragma unroll
                    for (int e = 0; e < 4; e++) {
                        float xn = q[e] * gw + gb;
                        float u = xn + 0.044715f * xn * xn * xn;
                        q[e] = xn / (1.f + __expf(-1.5957691216057308f * u));
                    }
                    r[kk] = make_float4(q[0], q[1], q[2], q[3]);
                }
            }
#pragma unroll
            for (int e = 0; e < 4; e++) {
                const float* f0 = reinterpret_cast<const float*>(&r[0]);
                const float* f1 = reinterpret_cast<const float*>(&r[1]);
                const float* f2 = reinterpret_cast<const float*>(&r[2]);
                const float* f3 = reinterpret_cast<const float*>(&r[3]);
                uint2 u;
                u.x = h2u(__floats2half2_rn(f0[e], f1[e]));
                u.y = h2u(__floats2half2_rn(f2[e], f3[e]));
                *reinterpret_cast<uint2*>(&sA[(v4 * 4 + e) * SAPAD + kb * 8 + half * 4]) = u;
            }
        }
    }
    // ---- stage B: [64 j][64 k] fp16 transpose of g_wtT. threads 0..127
    if (tid < 128) {
        int j4 = tid & 15;
        int kb = tid >> 4;
#pragma unroll
        for (int half = 0; half < 2; half++) {
            float4 r[4];
#pragma unroll
            for (int kk = 0; kk < 4; kk++) {
                int k = kb * 8 + half * 4 + kk;
                r[kk] = *reinterpret_cast<const float4*>(&g_wtT[k * NJP + jt * 64 + j4 * 4]);
            }
#pragma unroll
            for (int e = 0; e < 4; e++) {
                const float* f0 = reinterpret_cast<const float*>(&r[0]);
                const float* f1 = reinterpret_cast<const float*>(&r[1]);
                const float* f2 = reinterpret_cast<const float*>(&r[2]);
                const float* f3 = reinterpret_cast<const float*>(&r[3]);
                uint2 u;
                u.x = h2u(__floats2half2_rn(f0[e], f1[e]));
                u.y = h2u(__floats2half2_rn(f2[e], f3[e]));
                *reinterpret_cast<uint2*>(&sB[(j4 * 4 + e) * SAPAD + kb * 8 + half * 4]) = u;
            }
        }
    }
    __syncthreads();

    // ---- mma: warp w computes m32 x n32
    int w = tid >> 5, lane = tid & 31;
    int g = lane >> 2, t4 = lane & 3;
    int m0 = (w >> 1) * 32, n0 = (w & 1) * 32;
    float c[2][4][4];
#pragma unroll
    for (int mi = 0; mi < 2; mi++)
#pragma unroll
        for (int ni = 0; ni < 4; ni++)
#pragma unroll
            for (int e = 0; e < 4; e++) c[mi][ni][e] = 0.f;

#pragma unroll
    for (int kk = 0; kk < 4; kk++) {
        int k0 = kk * 16;
        unsigned a[2][4], b[4][2];
#pragma unroll
        for (int mi = 0; mi < 2; mi++) {
            int r = m0 + mi * 16;
            a[mi][0] = *reinterpret_cast<unsigned*>(&sA[(r + g) * SAPAD + k0 + 2 * t4]);
            a[mi][1] = *reinterpret_cast<unsigned*>(&sA[(r + 8 + g) * SAPAD + k0 + 2 * t4]);
            a[mi][2] = *reinterpret_cast<unsigned*>(&sA[(r + g) * SAPAD + k0 + 8 + 2 * t4]);
            a[mi][3] = *reinterpret_cast<unsigned*>(&sA[(r + 8 + g) * SAPAD + k0 + 8 + 2 * t4]);
        }
#pragma unroll
        for (int ni = 0; ni < 4; ni++) {
            int jr = n0 + ni * 8 + g;
            b[ni][0] = *reinterpret_cast<unsigned*>(&sB[jr * SAPAD + k0 + 2 * t4]);
            b[ni][1] = *reinterpret_cast<unsigned*>(&sB[jr * SAPAD + k0 + 8 + 2 * t4]);
        }
#pragma unroll
        for (int mi = 0; mi < 2; mi++)
#pragma unroll
            for (int ni = 0; ni < 4; ni++)
                mma16816(c[mi][ni], a[mi], b[ni]);
    }
    __syncthreads();   // operand reads done; reuse smem as sC

#pragma unroll
    for (int mi = 0; mi < 2; mi++)
#pragma unroll
        for (int ni = 0; ni < 4; ni++) {
            int r = m0 + mi * 16 + g;
            int cc = n0 + ni * 8 + 2 * t4;
            *reinterpret_cast<float2*>(&sC[r * SCPAD + cc]) =
                make_float2(c[mi][ni][0], c[mi][ni][1]);
            *reinterpret_cast<float2*>(&sC[(r + 8) * SCPAD + cc]) =
                make_float2(c[mi][ni][2], c[mi][ni][3]);
        }
    __syncthreads();

    // ---- epilogue
    int tx = tid & 15, ty = tid >> 4;
    float acc[8][4];
#pragma unroll
    for (int vi = 0; vi < 8; vi++) {
        int vloc = ((vi & 4) << 4) + tx * 4 + (vi & 3);
        float4 q = *reinterpret_cast<float4*>(&sC[vloc * SCPAD + ty * 4]);
        acc[vi][0] = q.x; acc[vi][1] = q.y; acc[vi][2] = q.z; acc[vi][3] = q.w;
    }

    if (jt == 0) {
        int o = ty * 4;
        int gg = o >> 5, ch = o & 31;
        float4 b4 = *reinterpret_cast<const float4*>(&g_bias[o]);
#pragma unroll
        for (int vi = 0; vi < 8; vi++) {
            int v = vbase + ((vi & 4) << 4) + tx * 4 + (vi & 3);
            int iz = v >> 10, iy = (v >> 5) & 31, ix = v & 31;
            int pos = (((gg * DP2 + iz + 2) * DP2 + iy + 2) * DP2 + ix + 2);
            __half2 h01 = __floats2half2_rn(acc[vi][0] + b4.x, acc[vi][1] + b4.y);
            __half2 h23 = __floats2half2_rn(acc[vi][2] + b4.z, acc[vi][3] + b4.w);
            uint2 u;
            u.x = h2u(h01);
            u.y = h2u(h23);
            *reinterpret_cast<uint2*>(&g_xph[(pos << 5) + ch]) = u;
        }
    } else {
        int pb0 = permv(vbase + tx * 4);        // x-quad -> contiguous 4 in perm
        int pb1 = permv(vbase + 64 + tx * 4);
#pragma unroll
        for (int jj = 0; jj < 4; jj++) {
            int j = jt * 64 + ty * 4 + jj;
            float* dst;
            if (j < 226)      dst = g_off  + (j - 64)  * NVOX;
            else if (j < 280) dst = g_mask + (j - 226) * NVOX;
            else continue;
            float bj = g_bias[j];
            *reinterpret_cast<float4*>(dst + pb0) =
                make_float4(acc[0][jj] + bj, acc[1][jj] + bj,
                            acc[2][jj] + bj, acc[3][jj] + bj);
            *reinterpret_cast<float4*>(dst + pb1) =
                make_float4(acc[4][jj] + bj, acc[5][jj] + bj,
                            acc[6][jj] + bj, acc[7][jj] + bj);
        }
    }
}

// ---------------------------------------------------------------------------
// Kernel 4: deformable sampling, SMEM window + HFMA2 inner loop.
// Tile-permuted g_off/g_mask: staging rows are 256B-contiguous.
// Result transposed through smem (aliases window buffer) -> coalesced
// c-row stores into tile-permuted g_samp.
// ---------------------------------------------------------------------------
__global__ void __launch_bounds__(256) k_samp() {
    int bid = blockIdx.x;            // 1024 = 512 tiles x 2 groups
    int gi = bid & 1;
    int tile = bid >> 1;
    int tbx = tile & 7, tby = (tile >> 3) & 7, tbz = tile >> 6;
    int tid = threadIdx.x;

    __shared__ __align__(16) char winbuf[8 * 8 * 8 * GC * 2];  // 32KB
    __half* s_win = reinterpret_cast<__half*>(winbuf);
    float (*s_acc)[64] = reinterpret_cast<float(*)[64]>(winbuf);  // aliased later
    __shared__ float s_off[64][81];
    __shared__ float s_m[64][28];

    int W0x = tbx * 4, W0y = tby * 4, W0z = tbz * 4;

    {
        const uint4* src = reinterpret_cast<const uint4*>(g_xph + (size_t)gi * HVOL);
        uint4* dst = reinterpret_cast<uint4*>(s_win);
#pragma unroll
        for (int i = 0; i < 8; i++) {
            int idx4 = i * 256 + tid;
            int pos = idx4 >> 2, q = idx4 & 3;
            int lz = pos >> 6, rem = pos & 63, ly = rem >> 3, lx = rem & 7;
            int gp = ((W0z + lz) * DP2 + W0y + ly) * DP2 + W0x + lx;
            dst[idx4] = src[gp * 4 + q];
        }
    }
    // tile-contiguous staging: row base = tile*64
    for (int idx = tid; idx < 64 * 81; idx += 256) {
        int vl = idx & 63, j = idx >> 6;
        s_off[vl][j] = g_off[(gi * 81 + j) * NVOX + tile * 64 + vl];
    }
    for (int idx = tid; idx < 64 * 27; idx += 256) {
        int vl = idx & 63, j = idx >> 6;
        s_m[vl][j] = g_mask[(gi * 27 + j) * NVOX + tile * 64 + vl];
    }
    __syncthreads();

    if (tid < 64) {
        float* m = s_m[tid];
        float mx = -1e30f;
#pragma unroll
        for (int p = 0; p < NP; p++) mx = fmaxf(mx, m[p]);
        float s = 0.f;
#pragma unroll
        for (int p = 0; p < NP; p++) { float e = __expf(m[p] - mx); m[p] = e; s += e; }
        float inv = 1.f / s;
#pragma unroll
        for (int p = 0; p < NP; p++) m[p] *= inv;
    }
    __syncthreads();

    int vv = tid >> 2;               // local voxel 0..63 (= perm local id)
    int c8 = tid & 3;
    int lxv = vv & 3, lyv = (vv >> 2) & 3, lzv = vv >> 4;

    const float4* win4 = reinterpret_cast<const float4*>(s_win);
    const float4* vol4 = reinterpret_cast<const float4*>(g_xph) + (size_t)gi * HVOL4 + c8;
    const float* offp = s_off[vv];
    const float* mp   = s_m[vv];

    float acc[8];
#pragma unroll
    for (int e = 0; e < 8; e++) acc[e] = 0.f;

    int kx = 0, ky = 0, kz = 0;
#pragma unroll 1
    for (int p = 0; p < NP; p++) {
        float ox = offp[p * 3 + 0];
        float oy = offp[p * 3 + 1];
        float oz = offp[p * 3 + 2];
        float sx = (float)(lxv + kx + 1) + 0.25f * ox;
        float sy = (float)(lyv + ky + 1) + 0.5f  * oy;
        float sz = (float)(lzv + kz + 1) + 0.5f  * oz;
        if (++kx == 3) { kx = 0; if (++ky == 3) { ky = 0; ++kz; } }

        float xf = floorf(sx), yf = floorf(sy), zf = floorf(sz);
        float fx = sx - xf, fy = sy - yf, fz = sz - zf;
        int x0 = (int)xf, y0 = (int)yf, z0 = (int)zf;

        float4 t000, t001, t010, t011, t100, t101, t110, t111;
        if ((unsigned)x0 < 7u && (unsigned)y0 < 7u && (unsigned)z0 < 7u) {
            int p000 = ((z0 * 8 + y0) * 8 + x0) * 4 + c8;
            t000 = win4[p000];       t001 = win4[p000 + 4];
            t010 = win4[p000 + 32];  t011 = win4[p000 + 36];
            t100 = win4[p000 + 256]; t101 = win4[p000 + 260];
            t110 = win4[p000 + 288]; t111 = win4[p000 + 292];
        } else {
            int gx0 = x0 + W0x, gy0 = y0 + W0y, gz0 = z0 + W0z;
            int x0c = min(max(gx0, 0), DP2 - 1),     y0c = min(max(gy0, 0), DP2 - 1);
            int z0c = min(max(gz0, 0), DP2 - 1);
            int x1c = min(max(gx0 + 1, 0), DP2 - 1), y1c = min(max(gy0 + 1, 0), DP2 - 1);
            int z1c = min(max(gz0 + 1, 0), DP2 - 1);
            int zy00 = (z0c * DP2 + y0c) * DP2;
            int zy01 = (z0c * DP2 + y1c) * DP2;
            int zy10 = (z1c * DP2 + y0c) * DP2;
            int zy11 = (z1c * DP2 + y1c) * DP2;
            t000 = vol4[(zy00 + x0c) << 2]; t001 = vol4[(zy00 + x1c) << 2];
            t010 = vol4[(zy01 + x0c) << 2]; t011 = vol4[(zy01 + x1c) << 2];
            t100 = vol4[(zy10 + x0c) << 2]; t101 = vol4[(zy10 + x1c) << 2];
            t110 = vol4[(zy11 + x0c) << 2]; t111 = vol4[(zy11 + x1c) << 2];
        }

        float gx1 = fx, gx0 = 1.f - fx;
        float gy1 = fy, gy0 = 1.f - fy;
        float gz1 = fz, gz0 = 1.f - fz;
        float w00 = gz0 * gy0, w01 = gz0 * gy1, w10 = gz1 * gy0, w11 = gz1 * gy1;

        __half2 h0 = __float2half2_rn(0.f), h1 = h0, h2 = h0, h3 = h0;
#define TAPH(T, W) { \
        __half2 wh = __float2half2_rn(W); \
        const __half2* hh = reinterpret_cast<const __half2*>(&T); \
        h0 = __hfma2(wh, hh[0], h0); h1 = __hfma2(wh, hh[1], h1); \
        h2 = __hfma2(wh, hh[2], h2); h3 = __hfma2(wh, hh[3], h3); }
        TAPH(t000, w00 * gx0) TAPH(t001, w00 * gx1)
        TAPH(t010, w01 * gx0) TAPH(t011, w01 * gx1)
        TAPH(t100, w10 * gx0) TAPH(t101, w10 * gx1)
        TAPH(t110, w11 * gx0) TAPH(t111, w11 * gx1)
#undef TAPH

        float m = mp[p];
        float2 f0 = __half22float2(h0);
        float2 f1 = __half22float2(h1);
        float2 f2 = __half22float2(h2);
        float2 f3 = __half22float2(h3);
        acc[0] = fmaf(m, f0.x, acc[0]); acc[1] = fmaf(m, f0.y, acc[1]);
        acc[2] = fmaf(m, f1.x, acc[2]); acc[3] = fmaf(m, f1.y, acc[3]);
        acc[4] = fmaf(m, f2.x, acc[4]); acc[5] = fmaf(m, f2.y, acc[5]);
        acc[6] = fmaf(m, f3.x, acc[6]); acc[7] = fmaf(m, f3.y, acc[7]);
    }

    // transpose through smem (window no longer needed), then coalesced store
    __syncthreads();
#pragma unroll
    for (int e = 0; e < 8; e++)
        s_acc[c8 * 8 + e][vv] = acc[e];
    __syncthreads();

    for (int idx = tid; idx < 32 * 64; idx += 256) {
        int c = idx >> 6, vl = idx & 63;
        g_samp[(gi * GC + c) * NVOX + tile * 64 + vl] = s_acc[c][vl];
    }
}

// ---------------------------------------------------------------------------
// Kernel 5: output GEMM over permuted voxel index; epilogue un-permutes.
// ---------------------------------------------------------------------------
__global__ void __launch_bounds__(256)
k_out(const float* __restrict__ out_w, const float* __restrict__ out_b,
      float* __restrict__ out) {
    int vbase = blockIdx.x * 128;
    int tid = threadIdx.x;
    __shared__ float sA[64 * 128];
    __shared__ float sB[64 * 64];

#pragma unroll
    for (int i = 0; i < 4; i++) {
        int lin = i * 1024 + tid * 4;
        *reinterpret_cast<float4*>(&sB[lin]) =
            *reinterpret_cast<const float4*>(&out_w[lin]);
    }
#pragma unroll
    for (int i = 0; i < 8; i++) {
        int lin = i * 1024 + tid * 4;
        int k = lin >> 7, vl = lin & 127;
        *reinterpret_cast<float4*>(&sA[lin]) =
            *reinterpret_cast<const float4*>(&g_samp[k * NVOX + vbase + vl]);
    }
    __syncthreads();

    int tx = tid & 15, ty = tid >> 4;
    float acc[8][4];
#pragma unroll
    for (int i = 0; i < 8; i++)
#pragma unroll
        for (int j = 0; j < 4; j++) acc[i][j] = 0.f;

    const float4* A4 = reinterpret_cast<const float4*>(sA);
    const float4* B4 = reinterpret_cast<const float4*>(sB);
#pragma unroll 8
    for (int k = 0; k < 64; k++) {
        float4 a0 = A4[k * 32 + tx];
        float4 a1 = A4[k * 32 + 16 + tx];
        float4 b  = B4[k * 16 + ty];
        float av[8] = {a0.x, a0.y, a0.z, a0.w, a1.x, a1.y, a1.z, a1.w};
        float bv[4] = {b.x, b.y, b.z, b.w};
#pragma unroll
        for (int i = 0; i < 8; i++)
#pragma unroll
            for (int j = 0; j < 4; j++)
                acc[i][j] = fmaf(av[i], bv[j], acc[i][j]);
    }

    float4 b4 = *reinterpret_cast<const float4*>(&out_b[ty * 4]);
#pragma unroll
    for (int vi = 0; vi < 8; vi++) {
        int vp = vbase + ((vi & 4) << 4) + tx * 4 + (vi & 3);
        // un-permute: tile-major -> linear voxel
        int t = vp >> 6, l = vp & 63;
        int vr = ((((t >> 6) << 2) + (l >> 4)) << 10)
               + (((((t >> 3) & 7) << 2) + ((l >> 2) & 3)) << 5)
               + (((t & 7) << 2) + (l & 3));
        *reinterpret_cast<float4*>(&out[vr * NC + ty * 4]) =
            make_float4(acc[vi][0] + b4.x, acc[vi][1] + b4.y,
                        acc[vi][2] + b4.z, acc[vi][3] + b4.w);
    }
}

// ---------------------------------------------------------------------------
extern "C" void kernel_launch(void* const* d_in, const int* in_sizes, int n_in,
                              void* d_out, int out_size) {
    const float* x      = (const float*)d_in[0];
    const float* dw_w   = (const float*)d_in[1];
    const float* gn_w   = (const float*)d_in[2];
    const float* gn_b   = (const float*)d_in[3];
    const float* inp_w  = (const float*)d_in[4];
    const float* inp_b  = (const float*)d_in[5];
    const float* off_w  = (const float*)d_in[6];
    const float* off_b  = (const float*)d_in[7];
    const float* mask_w = (const float*)d_in[8];
    const float* mask_b = (const float*)d_in[9];
    const float* out_w  = (const float*)d_in[10];
    const float* out_b  = (const float*)d_in[11];
    float* out = (float*)d_out;

    k_init<<<(NC * NJP + 255) / 256, 256>>>(inp_w, off_w, mask_w, inp_b, off_b, mask_b);
    k_dw<<<dim3(32, 64), 256>>>(x, dw_w);
    k_stats<<<1, 1024>>>();
    k_point<<<dim3(NVOX / 128, 5), 256>>>(x, gn_w, gn_b);
    k_samp<<<1024, 256>>>();
    k_out<<<NVOX / 128, 256>>>(out_w, out_b, out);
}